// round 2
// baseline (speedup 1.0000x reference)
#include <cuda_runtime.h>
#include <cstdint>
#include <cstdio>

#define T_  4096
#define B_  32
#define D_  512
#define H_  256
#define G4_ 1024            // 4*H
#define P_  74              // time-chunks per batch row
#define GS_ 16              // streams per block
#define NBLK_ ((B_ * P_) / GS_)   // 148 blocks

// ---------------- scratch (static device globals; no allocations) ----------
__device__ float g_xw[(size_t)B_ * T_ * G4_];   // [b][t][4H]  (512 MB)
__device__ float g_WT[H_ * G4_];                // W_hh transposed: [k][g]
__device__ float g_bb[G4_];                     // b_ih + b_hh
__device__ int   g_bound[B_][P_ + 1];           // chunk boundaries per batch row

// ---------------- stage 0: chunk boundaries at reset points ----------------
__global__ void k_bounds(const int* __restrict__ reset) {
    int b = blockIdx.x;
    int k = threadIdx.x;
    if (k == 0) {
        g_bound[b][0] = 0;
    } else if (k < P_) {
        int t = (k * T_) / P_;
        while (t < T_ && reset[t * B_ + b] == 0) t++;
        g_bound[b][k] = t;          // either a reset point (state=0) or T
    } else if (k == P_) {
        g_bound[b][P_] = T_;
    }
}

// ---------------- stage 0b: transpose W_hh, fuse biases --------------------
__global__ void k_prep(const float* __restrict__ Whh,
                       const float* __restrict__ bih,
                       const float* __restrict__ bhh) {
    int idx = blockIdx.x * blockDim.x + threadIdx.x;
    if (idx < H_ * G4_) {
        int g = idx % G4_;
        int k = idx / G4_;
        g_WT[idx] = Whh[g * H_ + k];
    }
    if (idx < G4_) g_bb[idx] = bih[idx] + bhh[idx];
}

// ---------------- stage 1: xW GEMM  (M=T*B, N=4H, K=D) ---------------------
#define BM 128
#define BN 128
#define BK 16

__global__ __launch_bounds__(256) void k_gemm(const float* __restrict__ A,
                                              const float* __restrict__ Bw) {
    __shared__ float As[2][BK][BM];
    __shared__ float Bs[2][BK][BN];

    const int m0 = blockIdx.y * BM;
    const int n0 = blockIdx.x * BN;
    const int tid = threadIdx.x;
    const int tx = tid % 16;
    const int ty = tid / 16;

    float acc[8][8];
#pragma unroll
    for (int i = 0; i < 8; i++)
#pragma unroll
        for (int j = 0; j < 8; j++) acc[i][j] = 0.f;

    // tile loaders: 128 rows x 16 cols = 512 float4, 2 per thread
#define LOAD_TILE(buf, k0)                                                      \
    {                                                                           \
        _Pragma("unroll")                                                       \
        for (int q = tid; q < 512; q += 256) {                                  \
            int row = q >> 2, cc = q & 3;                                       \
            float4 va = *(const float4*)(A + (size_t)(m0 + row) * D_ + (k0) + cc * 4); \
            As[buf][cc * 4 + 0][row] = va.x;                                    \
            As[buf][cc * 4 + 1][row] = va.y;                                    \
            As[buf][cc * 4 + 2][row] = va.z;                                    \
            As[buf][cc * 4 + 3][row] = va.w;                                    \
            float4 vb = *(const float4*)(Bw + (size_t)(n0 + row) * D_ + (k0) + cc * 4); \
            Bs[buf][cc * 4 + 0][row] = vb.x;                                    \
            Bs[buf][cc * 4 + 1][row] = vb.y;                                    \
            Bs[buf][cc * 4 + 2][row] = vb.z;                                    \
            Bs[buf][cc * 4 + 3][row] = vb.w;                                    \
        }                                                                       \
    }

    LOAD_TILE(0, 0)
    __syncthreads();

    const int NKT = D_ / BK;   // 32
    for (int kt = 0; kt < NKT; kt++) {
        int cur = kt & 1;
        int nxt = cur ^ 1;
        if (kt + 1 < NKT) LOAD_TILE(nxt, (kt + 1) * BK)
#pragma unroll
        for (int k = 0; k < BK; k++) {
            float a[8], b[8];
            *(float4*)(a)     = *(const float4*)&As[cur][k][ty * 8];
            *(float4*)(a + 4) = *(const float4*)&As[cur][k][ty * 8 + 4];
            *(float4*)(b)     = *(const float4*)&Bs[cur][k][tx * 8];
            *(float4*)(b + 4) = *(const float4*)&Bs[cur][k][tx * 8 + 4];
#pragma unroll
            for (int i = 0; i < 8; i++)
#pragma unroll
                for (int j = 0; j < 8; j++) acc[i][j] += a[i] * b[j];
        }
        __syncthreads();
    }

    // epilogue: + bias, scatter row m=t*B+b -> g_xw[b][t][:]
    float bias[8];
#pragma unroll
    for (int j = 0; j < 8; j++) bias[j] = g_bb[n0 + tx * 8 + j];

#pragma unroll
    for (int i = 0; i < 8; i++) {
        int m = m0 + ty * 8 + i;
        int t = m >> 5;        // m / B_
        int b = m & 31;        // m % B_
        float* dst = g_xw + ((size_t)b * T_ + t) * G4_ + n0 + tx * 8;
        float4 v0, v1;
        v0.x = acc[i][0] + bias[0]; v0.y = acc[i][1] + bias[1];
        v0.z = acc[i][2] + bias[2]; v0.w = acc[i][3] + bias[3];
        v1.x = acc[i][4] + bias[4]; v1.y = acc[i][5] + bias[5];
        v1.z = acc[i][6] + bias[6]; v1.w = acc[i][7] + bias[7];
        *(float4*)(dst)     = v0;
        *(float4*)(dst + 4) = v1;
    }
}

// ---------------- stage 2: segment-parallel recurrence ---------------------
__device__ __forceinline__ float sigf(float x) {
    return 1.f / (1.f + __expf(-x));
}

__global__ __launch_bounds__(256, 1) void k_recur(const int* __restrict__ reset,
                                                  const float* __restrict__ Wp,
                                                  const float* __restrict__ bp,
                                                  float* __restrict__ out) {
    __shared__ float h_sm[2][GS_][H_];     // double-buffered hidden states
    __shared__ float red[2][GS_][8];       // per-warp projection partials
    __shared__ int s_start[GS_], s_end[GS_], s_b[GS_];

    const int j = threadIdx.x;             // hidden unit 0..255
    const int lane = j & 31;
    const int warp = j >> 5;

    if (j < GS_) {
        int sid = blockIdx.x * GS_ + j;
        int b = sid / P_;
        int k = sid % P_;
        s_start[j] = g_bound[b][k];
        s_end[j]   = g_bound[b][k + 1];
        s_b[j]     = b;
    }
#pragma unroll
    for (int s = 0; s < GS_; s++) h_sm[0][s][j] = 0.f;
    float c[GS_];
#pragma unroll
    for (int s = 0; s < GS_; s++) c[s] = 0.f;
    __syncthreads();

    int maxlen = 0;
#pragma unroll
    for (int s = 0; s < GS_; s++) {
        int len = s_end[s] - s_start[s];
        maxlen = max(maxlen, len);
    }

    const float wp  = Wp[j];
    const float bpv = bp[0];

    for (int r = 0; r < maxlen; r++) {
        const int rb = r & 1;

        float a0[GS_], a1[GS_], a2[GS_], a3[GS_];
#pragma unroll
        for (int s = 0; s < GS_; s++) { a0[s] = 0.f; a1[s] = 0.f; a2[s] = 0.f; a3[s] = 0.f; }

        // gates += h @ W_hh^T  for all 16 streams, weights reused in registers
        for (int kk = 0; kk < H_; kk += 4) {
            float w0[4], w1[4], w2[4], w3[4];
#pragma unroll
            for (int u = 0; u < 4; u++) {
                const float* wr = g_WT + (size_t)(kk + u) * G4_ + j;
                w0[u] = wr[0];
                w1[u] = wr[256];
                w2[u] = wr[512];
                w3[u] = wr[768];
            }
#pragma unroll
            for (int s = 0; s < GS_; s++) {
                float4 h4 = *(const float4*)&h_sm[rb][s][kk];
                a0[s] += w0[0] * h4.x; a0[s] += w0[1] * h4.y;
                a0[s] += w0[2] * h4.z; a0[s] += w0[3] * h4.w;
                a1[s] += w1[0] * h4.x; a1[s] += w1[1] * h4.y;
                a1[s] += w1[2] * h4.z; a1[s] += w1[3] * h4.w;
                a2[s] += w2[0] * h4.x; a2[s] += w2[1] * h4.y;
                a2[s] += w2[2] * h4.z; a2[s] += w2[3] * h4.w;
                a3[s] += w3[0] * h4.x; a3[s] += w3[1] * h4.y;
                a3[s] += w3[2] * h4.z; a3[s] += w3[3] * h4.w;
            }
        }

#pragma unroll
        for (int s = 0; s < GS_; s++) {
            int t = s_start[s] + r;
            if (t < s_end[s]) {            // uniform across the block per s
                int b = s_b[s];
                const float* xr = g_xw + ((size_t)b * T_ + t) * G4_ + j;
                float keep = (reset[t * B_ + b] != 0) ? 0.f : 1.f;
                float gi = xr[0]   + keep * a0[s];
                float gf = xr[256] + keep * a1[s];
                float gg = xr[512] + keep * a2[s];
                float go = xr[768] + keep * a3[s];
                float cc = sigf(gf) * (c[s] * keep) + sigf(gi) * tanhf(gg);
                float hh = sigf(go) * tanhf(cc);
                c[s] = cc;
                h_sm[rb ^ 1][s][j] = hh;
                // projection partial: sum_j h_j * Wp_j
                float p = hh * wp;
#pragma unroll
                for (int off = 16; off; off >>= 1)
                    p += __shfl_down_sync(0xffffffffu, p, off);
                if (lane == 0) red[rb][s][warp] = p;
            } else {
                h_sm[rb ^ 1][s][j] = 0.f;
            }
        }
        __syncthreads();

        if (j < GS_) {
            int s = j;
            int t = s_start[s] + r;
            if (t < s_end[s]) {
                float sum = bpv;
#pragma unroll
                for (int w2 = 0; w2 < 8; w2++) sum += red[rb][s][w2];
                out[t * B_ + s_b[s]] = sum;
            }
        }
    }
}

// ---------------- launch ----------------------------------------------------
extern "C" void kernel_launch(void* const* d_in, const int* in_sizes, int n_in,
                              void* d_out, int out_size) {
    const float* x     = (const float*)d_in[0];
    const int*   reset = (const int*)  d_in[1];
    const float* Wih   = (const float*)d_in[2];
    const float* Whh   = (const float*)d_in[3];
    const float* bih   = (const float*)d_in[4];
    const float* bhh   = (const float*)d_in[5];
    const float* Wp    = (const float*)d_in[6];
    const float* bp    = (const float*)d_in[7];
    float* out = (float*)d_out;

    k_bounds<<<B_, 128>>>(reset);
    k_prep<<<(H_ * G4_ + 255) / 256, 256>>>(Whh, bih, bhh);

    dim3 grid(G4_ / BN, (T_ * B_) / BM);
    k_gemm<<<grid, 256>>>(x, Wih);

    k_recur<<<NBLK_, 256>>>(reset, Wp, bp, out);
}

// round 3
// speedup vs baseline: 1.5818x; 1.5818x over previous
#include <cuda_runtime.h>
#include <cstdint>
#include <cstdio>

#define T_  4096
#define B_  32
#define D_  512
#define H_  256
#define G4_ 1024            // 4*H
#define P_  74              // time-chunks per batch row
#define GS_ 16              // streams per block
#define SPG_ 8              // streams per thread-group in k_recur
#define NBLK_ ((B_ * P_) / GS_)   // 148 blocks

// ---------------- scratch (static device globals; no allocations) ----------
__device__ float g_xw[(size_t)B_ * T_ * G4_];   // [b][t][4H]  (512 MB)
__device__ float g_WT[H_ * G4_];                // W_hh transposed: [k][g]
__device__ float g_bb[G4_];                     // b_ih + b_hh
__device__ int   g_bound[B_][P_ + 1];           // chunk boundaries per batch row

// ---------------- stage 0: chunk boundaries at reset points ----------------
__global__ void k_bounds(const int* __restrict__ reset) {
    int b = blockIdx.x;
    int k = threadIdx.x;
    if (k == 0) {
        g_bound[b][0] = 0;
    } else if (k < P_) {
        int t = (k * T_) / P_;
        while (t < T_ && reset[t * B_ + b] == 0) t++;
        g_bound[b][k] = t;          // either a reset point (state=0) or T
    } else if (k == P_) {
        g_bound[b][P_] = T_;
    }
}

// ---------------- stage 0b: transpose W_hh, fuse biases --------------------
__global__ void k_prep(const float* __restrict__ Whh,
                       const float* __restrict__ bih,
                       const float* __restrict__ bhh) {
    int idx = blockIdx.x * blockDim.x + threadIdx.x;
    if (idx < H_ * G4_) {
        int g = idx % G4_;
        int k = idx / G4_;
        g_WT[idx] = Whh[g * H_ + k];
    }
    if (idx < G4_) g_bb[idx] = bih[idx] + bhh[idx];
}

// ---------------- stage 1: xW GEMM via tf32 mma.sync -----------------------
// M = T*B = 131072, N = 1024, K = 512.  Tile 128x128x32, 256 threads (8 warps
// in a 4x2 grid, warp tile 32x64). XOR-swizzled smem, manual double buffer.
#define GBM 128
#define GBN 128
#define GBK 32
#define BOFF (2 * GBM * GBK)   // Bs offset in dynamic smem (floats)

__device__ __forceinline__ float tf32r(float x) {
    float r;
    asm("cvt.rna.tf32.f32 %0, %1;" : "=f"(r) : "f"(x));
    return r;
}

__device__ __forceinline__ void mma_tf32(float* c, const uint32_t* a, const uint32_t* b) {
    asm volatile(
        "mma.sync.aligned.m16n8k8.row.col.f32.tf32.tf32.f32 "
        "{%0,%1,%2,%3},{%4,%5,%6,%7},{%8,%9},{%0,%1,%2,%3};"
        : "+f"(c[0]), "+f"(c[1]), "+f"(c[2]), "+f"(c[3])
        : "r"(a[0]), "r"(a[1]), "r"(a[2]), "r"(a[3]), "r"(b[0]), "r"(b[1]));
}

__global__ __launch_bounds__(256) void k_gemm_tf32(const float* __restrict__ A,
                                                   const float* __restrict__ Bw) {
    extern __shared__ float sm[];   // As: [2][128][32] swizzled, Bs: same, 64 KB

    const int tid  = threadIdx.x;
    const int warp = tid >> 5;
    const int lane = tid & 31;
    const int wm   = warp >> 1;          // 0..3
    const int wn   = warp & 1;           // 0..1
    const int gid  = lane >> 2;          // groupID 0..7
    const int qid  = lane & 3;           // thread-in-group 0..3
    const int m0   = blockIdx.y * GBM;
    const int n0   = blockIdx.x * GBN;

    // copy mapping: row = tid>>1 (0..127), col4 base = (tid&1)*4, 4 float4/thread
    const int crow = tid >> 1;
    const int cc4  = (tid & 1) * 4;
    const float* gA = A  + (size_t)(m0 + crow) * D_ + cc4 * 4;
    const float* gB = Bw + (size_t)(n0 + crow) * D_ + cc4 * 4;

    float acc[2][8][4];
#pragma unroll
    for (int i = 0; i < 2; i++)
#pragma unroll
        for (int j = 0; j < 8; j++)
#pragma unroll
            for (int q = 0; q < 4; q++) acc[i][j][q] = 0.f;

    float4 ra[4], rb[4];

#define LOADG(k0)                                                   \
    {                                                               \
        _Pragma("unroll")                                           \
        for (int i = 0; i < 4; i++) {                               \
            ra[i] = *(const float4*)(gA + (k0) + i * 4);            \
            rb[i] = *(const float4*)(gB + (k0) + i * 4);            \
        }                                                           \
    }

#define STORES(buf)                                                             \
    {                                                                           \
        _Pragma("unroll")                                                       \
        for (int i = 0; i < 4; i++) {                                           \
            int sw = ((cc4 + i) ^ (crow & 7)) * 4;                              \
            float4 va;                                                          \
            va.x = tf32r(ra[i].x); va.y = tf32r(ra[i].y);                       \
            va.z = tf32r(ra[i].z); va.w = tf32r(ra[i].w);                       \
            *(float4*)&sm[((buf) * GBM + crow) * GBK + sw] = va;                \
            float4 vb;                                                          \
            vb.x = tf32r(rb[i].x); vb.y = tf32r(rb[i].y);                       \
            vb.z = tf32r(rb[i].z); vb.w = tf32r(rb[i].w);                       \
            *(float4*)&sm[BOFF + ((buf) * GBN + crow) * GBK + sw] = vb;         \
        }                                                                       \
    }

    LOADG(0)
    STORES(0)
    __syncthreads();

    const int NKT = D_ / GBK;   // 16
    for (int kt = 0; kt < NKT; kt++) {
        const int cur = kt & 1;
        if (kt + 1 < NKT) LOADG((kt + 1) * GBK)

#pragma unroll
        for (int kc = 0; kc < 4; kc++) {
            const int k4a = kc * 2;        // col>>2 for qid, (+1 for qid+4)
            uint32_t af[2][4], bf[8][2];
#pragma unroll
            for (int ma = 0; ma < 2; ma++) {
                int rw = wm * 32 + ma * 16 + gid;
                int b0 = (cur * GBM + rw) * GBK;
                int b8 = b0 + 8 * GBK;
                int x  = rw & 7;           // == (rw+8)&7
                af[ma][0] = __float_as_uint(sm[b0 + ((k4a)     ^ x) * 4 + qid]);
                af[ma][1] = __float_as_uint(sm[b8 + ((k4a)     ^ x) * 4 + qid]);
                af[ma][2] = __float_as_uint(sm[b0 + ((k4a + 1) ^ x) * 4 + qid]);
                af[ma][3] = __float_as_uint(sm[b8 + ((k4a + 1) ^ x) * 4 + qid]);
            }
#pragma unroll
            for (int na = 0; na < 8; na++) {
                int rn = wn * 64 + na * 8 + gid;
                int bb = BOFF + (cur * GBN + rn) * GBK;
                int x  = rn & 7;
                bf[na][0] = __float_as_uint(sm[bb + ((k4a)     ^ x) * 4 + qid]);
                bf[na][1] = __float_as_uint(sm[bb + ((k4a + 1) ^ x) * 4 + qid]);
            }
#pragma unroll
            for (int na = 0; na < 8; na++)
#pragma unroll
                for (int ma = 0; ma < 2; ma++)
                    mma_tf32(acc[ma][na], af[ma], bf[na]);
        }

        if (kt + 1 < NKT) STORES(cur ^ 1)
        __syncthreads();
    }

    // epilogue: +bias, scatter (m = t*B + b) -> g_xw[b][t][n]
#pragma unroll
    for (int na = 0; na < 8; na++) {
        const int n = n0 + wn * 64 + na * 8 + qid * 2;
        const float bi0 = g_bb[n];
        const float bi1 = g_bb[n + 1];
#pragma unroll
        for (int ma = 0; ma < 2; ma++) {
            int m1 = m0 + wm * 32 + ma * 16 + gid;
            int m2 = m1 + 8;
            {
                int t = m1 >> 5, b = m1 & 31;
                float2 v = { acc[ma][na][0] + bi0, acc[ma][na][1] + bi1 };
                *(float2*)(g_xw + ((size_t)b * T_ + t) * G4_ + n) = v;
            }
            {
                int t = m2 >> 5, b = m2 & 31;
                float2 v = { acc[ma][na][2] + bi0, acc[ma][na][3] + bi1 };
                *(float2*)(g_xw + ((size_t)b * T_ + t) * G4_ + n) = v;
            }
        }
    }
#undef LOADG
#undef STORES
}

// ---------------- stage 2: segment-parallel recurrence ---------------------
__device__ __forceinline__ float sigf(float x) {
    return 1.f / (1.f + __expf(-x));
}

__global__ __launch_bounds__(512, 1) void k_recur(const int* __restrict__ reset,
                                                  const float* __restrict__ Wp,
                                                  const float* __restrict__ bp,
                                                  float* __restrict__ out) {
    __shared__ float h_sm[2][GS_][H_];     // double-buffered hidden states
    __shared__ float red[2][GS_][8];       // per-warp projection partials
    __shared__ int s_start[GS_], s_end[GS_], s_b[GS_];

    const int tid   = threadIdx.x;
    const int grp   = tid >> 8;            // 0/1: which 8 streams
    const int j     = tid & 255;           // hidden unit 0..255
    const int lane  = tid & 31;
    const int warp8 = (tid >> 5) & 7;      // warp index within group
    const int sbase = grp * SPG_;

    if (tid < GS_) {
        int sid = blockIdx.x * GS_ + tid;
        int b = sid / P_;
        int k = sid % P_;
        s_start[tid] = g_bound[b][k];
        s_end[tid]   = g_bound[b][k + 1];
        s_b[tid]     = b;
    }
    if (tid < H_) {
#pragma unroll
        for (int s = 0; s < GS_; s++) h_sm[0][s][tid] = 0.f;
    }
    float c[SPG_];
#pragma unroll
    for (int s = 0; s < SPG_; s++) c[s] = 0.f;
    __syncthreads();

    int maxlen = 0;
#pragma unroll
    for (int s = 0; s < GS_; s++) {
        int len = s_end[s] - s_start[s];
        maxlen = max(maxlen, len);
    }

    const float wp  = Wp[j];
    const float bpv = bp[0];
    const float* __restrict__ wt = g_WT;

    for (int r = 0; r < maxlen; r++) {
        const int rb = r & 1;

        float a0[SPG_], a1[SPG_], a2[SPG_], a3[SPG_];
#pragma unroll
        for (int s = 0; s < SPG_; s++) { a0[s] = 0.f; a1[s] = 0.f; a2[s] = 0.f; a3[s] = 0.f; }

        // gates += h @ W_hh^T  for this group's 8 streams, weights in regs
        for (int kk = 0; kk < H_; kk += 4) {
            float w0[4], w1[4], w2[4], w3[4];
#pragma unroll
            for (int u = 0; u < 4; u++) {
                const float* wr = wt + (size_t)(kk + u) * G4_ + j;
                w0[u] = wr[0];
                w1[u] = wr[256];
                w2[u] = wr[512];
                w3[u] = wr[768];
            }
#pragma unroll
            for (int s = 0; s < SPG_; s++) {
                float4 h4 = *(const float4*)&h_sm[rb][sbase + s][kk];
                a0[s] += w0[0] * h4.x; a0[s] += w0[1] * h4.y;
                a0[s] += w0[2] * h4.z; a0[s] += w0[3] * h4.w;
                a1[s] += w1[0] * h4.x; a1[s] += w1[1] * h4.y;
                a1[s] += w1[2] * h4.z; a1[s] += w1[3] * h4.w;
                a2[s] += w2[0] * h4.x; a2[s] += w2[1] * h4.y;
                a2[s] += w2[2] * h4.z; a2[s] += w2[3] * h4.w;
                a3[s] += w3[0] * h4.x; a3[s] += w3[1] * h4.y;
                a3[s] += w3[2] * h4.z; a3[s] += w3[3] * h4.w;
            }
        }

#pragma unroll
        for (int s = 0; s < SPG_; s++) {
            const int ss = sbase + s;
            int t = s_start[ss] + r;
            if (t < s_end[ss]) {           // uniform across block per ss
                int b = s_b[ss];
                const float* xr = g_xw + ((size_t)b * T_ + t) * G4_ + j;
                float keep = (reset[t * B_ + b] != 0) ? 0.f : 1.f;
                float gi = xr[0]   + keep * a0[s];
                float gf = xr[256] + keep * a1[s];
                float gg = xr[512] + keep * a2[s];
                float go = xr[768] + keep * a3[s];
                float cc = sigf(gf) * (c[s] * keep) + sigf(gi) * tanhf(gg);
                float hh = sigf(go) * tanhf(cc);
                c[s] = cc;
                h_sm[rb ^ 1][ss][j] = hh;
                // projection partial: sum_j h_j * Wp_j
                float p = hh * wp;
#pragma unroll
                for (int off = 16; off; off >>= 1)
                    p += __shfl_down_sync(0xffffffffu, p, off);
                if (lane == 0) red[rb][ss][warp8] = p;
            } else {
                h_sm[rb ^ 1][ss][j] = 0.f;
            }
        }
        __syncthreads();

        if (tid < GS_) {
            int s = tid;
            int t = s_start[s] + r;
            if (t < s_end[s]) {
                float sum = bpv;
#pragma unroll
                for (int w2 = 0; w2 < 8; w2++) sum += red[rb][s][w2];
                out[t * B_ + s_b[s]] = sum;
            }
        }
    }
}

// ---------------- launch ----------------------------------------------------
extern "C" void kernel_launch(void* const* d_in, const int* in_sizes, int n_in,
                              void* d_out, int out_size) {
    const float* x     = (const float*)d_in[0];
    const int*   reset = (const int*)  d_in[1];
    const float* Wih   = (const float*)d_in[2];
    const float* Whh   = (const float*)d_in[3];
    const float* bih   = (const float*)d_in[4];
    const float* bhh   = (const float*)d_in[5];
    const float* Wp    = (const float*)d_in[6];
    const float* bp    = (const float*)d_in[7];
    float* out = (float*)d_out;

    k_bounds<<<B_, 128>>>(reset);
    k_prep<<<(H_ * G4_ + 255) / 256, 256>>>(Whh, bih, bhh);

    static int smem_set = 0;
    if (!smem_set) {
        cudaFuncSetAttribute(k_gemm_tf32,
                             cudaFuncAttributeMaxDynamicSharedMemorySize, 65536);
        smem_set = 1;
    }
    dim3 grid(G4_ / GBN, (T_ * B_) / GBM);
    k_gemm_tf32<<<grid, 256, 65536>>>(x, Wih);

    k_recur<<<NBLK_, 512>>>(reset, Wp, bp, out);
}

// round 4
// speedup vs baseline: 1.9453x; 1.2298x over previous
#include <cuda_runtime.h>
#include <cstdint>
#include <cstdio>

#define T_  4096
#define B_  32
#define D_  512
#define H_  256
#define G4_ 1024            // 4*H
#define P_  74              // time-chunks per batch row
#define GS_ 16              // streams per block
#define SPG_ 8              // streams per thread-group in k_recur
#define NPAIR_ 8            // stream pairs per block (GS_/2)
#define NBLK_ ((B_ * P_) / GS_)   // 148 blocks

// ---------------- scratch (static device globals; no allocations) ----------
__device__ float g_xw[(size_t)B_ * T_ * G4_];   // [b][t][4H]  (512 MB)
__device__ float g_WT[H_ * G4_];                // W_hh transposed: [k][g]
__device__ float g_bb[G4_];                     // b_ih + b_hh
__device__ int   g_bound[B_][P_ + 1];           // chunk boundaries per batch row

// ---------------- stage 0: chunk boundaries at reset points ----------------
__global__ void k_bounds(const int* __restrict__ reset) {
    int b = blockIdx.x;
    int k = threadIdx.x;
    if (k == 0) {
        g_bound[b][0] = 0;
    } else if (k < P_) {
        int t = (k * T_) / P_;
        while (t < T_ && reset[t * B_ + b] == 0) t++;
        g_bound[b][k] = t;          // either a reset point (state=0) or T
    } else if (k == P_) {
        g_bound[b][P_] = T_;
    }
}

// ---------------- stage 0b: transpose W_hh, fuse biases --------------------
__global__ void k_prep(const float* __restrict__ Whh,
                       const float* __restrict__ bih,
                       const float* __restrict__ bhh) {
    int idx = blockIdx.x * blockDim.x + threadIdx.x;
    if (idx < H_ * G4_) {
        int g = idx % G4_;
        int k = idx / G4_;
        g_WT[idx] = Whh[g * H_ + k];
    }
    if (idx < G4_) g_bb[idx] = bih[idx] + bhh[idx];
}

// ---------------- stage 1: xW GEMM via tf32 mma.sync -----------------------
#define GBM 128
#define GBN 128
#define GBK 32
#define BOFF (2 * GBM * GBK)   // Bs offset in dynamic smem (floats)

__device__ __forceinline__ float tf32r(float x) {
    float r;
    asm("cvt.rna.tf32.f32 %0, %1;" : "=f"(r) : "f"(x));
    return r;
}

__device__ __forceinline__ void mma_tf32(float* c, const uint32_t* a, const uint32_t* b) {
    asm volatile(
        "mma.sync.aligned.m16n8k8.row.col.f32.tf32.tf32.f32 "
        "{%0,%1,%2,%3},{%4,%5,%6,%7},{%8,%9},{%0,%1,%2,%3};"
        : "+f"(c[0]), "+f"(c[1]), "+f"(c[2]), "+f"(c[3])
        : "r"(a[0]), "r"(a[1]), "r"(a[2]), "r"(a[3]), "r"(b[0]), "r"(b[1]));
}

__global__ __launch_bounds__(256) void k_gemm_tf32(const float* __restrict__ A,
                                                   const float* __restrict__ Bw) {
    extern __shared__ float sm[];   // As: [2][128][32] swizzled, Bs: same, 64 KB

    const int tid  = threadIdx.x;
    const int warp = tid >> 5;
    const int lane = tid & 31;
    const int wm   = warp >> 1;          // 0..3
    const int wn   = warp & 1;           // 0..1
    const int gid  = lane >> 2;          // groupID 0..7
    const int qid  = lane & 3;           // thread-in-group 0..3
    const int m0   = blockIdx.y * GBM;
    const int n0   = blockIdx.x * GBN;

    const int crow = tid >> 1;
    const int cc4  = (tid & 1) * 4;
    const float* gA = A  + (size_t)(m0 + crow) * D_ + cc4 * 4;
    const float* gB = Bw + (size_t)(n0 + crow) * D_ + cc4 * 4;

    float acc[2][8][4];
#pragma unroll
    for (int i = 0; i < 2; i++)
#pragma unroll
        for (int j = 0; j < 8; j++)
#pragma unroll
            for (int q = 0; q < 4; q++) acc[i][j][q] = 0.f;

    float4 ra[4], rb[4];

#define LOADG(k0)                                                   \
    {                                                               \
        _Pragma("unroll")                                           \
        for (int i = 0; i < 4; i++) {                               \
            ra[i] = *(const float4*)(gA + (k0) + i * 4);            \
            rb[i] = *(const float4*)(gB + (k0) + i * 4);            \
        }                                                           \
    }

#define STORES(buf)                                                             \
    {                                                                           \
        _Pragma("unroll")                                                       \
        for (int i = 0; i < 4; i++) {                                           \
            int sw = ((cc4 + i) ^ (crow & 7)) * 4;                              \
            float4 va;                                                          \
            va.x = tf32r(ra[i].x); va.y = tf32r(ra[i].y);                       \
            va.z = tf32r(ra[i].z); va.w = tf32r(ra[i].w);                       \
            *(float4*)&sm[((buf) * GBM + crow) * GBK + sw] = va;                \
            float4 vb;                                                          \
            vb.x = tf32r(rb[i].x); vb.y = tf32r(rb[i].y);                       \
            vb.z = tf32r(rb[i].z); vb.w = tf32r(rb[i].w);                       \
            *(float4*)&sm[BOFF + ((buf) * GBN + crow) * GBK + sw] = vb;         \
        }                                                                       \
    }

    LOADG(0)
    STORES(0)
    __syncthreads();

    const int NKT = D_ / GBK;   // 16
    for (int kt = 0; kt < NKT; kt++) {
        const int cur = kt & 1;
        if (kt + 1 < NKT) LOADG((kt + 1) * GBK)

#pragma unroll
        for (int kc = 0; kc < 4; kc++) {
            const int k4a = kc * 2;
            uint32_t af[2][4], bf[8][2];
#pragma unroll
            for (int ma = 0; ma < 2; ma++) {
                int rw = wm * 32 + ma * 16 + gid;
                int b0 = (cur * GBM + rw) * GBK;
                int b8 = b0 + 8 * GBK;
                int x  = rw & 7;
                af[ma][0] = __float_as_uint(sm[b0 + ((k4a)     ^ x) * 4 + qid]);
                af[ma][1] = __float_as_uint(sm[b8 + ((k4a)     ^ x) * 4 + qid]);
                af[ma][2] = __float_as_uint(sm[b0 + ((k4a + 1) ^ x) * 4 + qid]);
                af[ma][3] = __float_as_uint(sm[b8 + ((k4a + 1) ^ x) * 4 + qid]);
            }
#pragma unroll
            for (int na = 0; na < 8; na++) {
                int rn = wn * 64 + na * 8 + gid;
                int bb = BOFF + (cur * GBN + rn) * GBK;
                int x  = rn & 7;
                bf[na][0] = __float_as_uint(sm[bb + ((k4a)     ^ x) * 4 + qid]);
                bf[na][1] = __float_as_uint(sm[bb + ((k4a + 1) ^ x) * 4 + qid]);
            }
#pragma unroll
            for (int na = 0; na < 8; na++)
#pragma unroll
                for (int ma = 0; ma < 2; ma++)
                    mma_tf32(acc[ma][na], af[ma], bf[na]);
        }

        if (kt + 1 < NKT) STORES(cur ^ 1)
        __syncthreads();
    }

#pragma unroll
    for (int na = 0; na < 8; na++) {
        const int n = n0 + wn * 64 + na * 8 + qid * 2;
        const float bi0 = g_bb[n];
        const float bi1 = g_bb[n + 1];
#pragma unroll
        for (int ma = 0; ma < 2; ma++) {
            int m1 = m0 + wm * 32 + ma * 16 + gid;
            int m2 = m1 + 8;
            {
                int t = m1 >> 5, b = m1 & 31;
                float2 v = { acc[ma][na][0] + bi0, acc[ma][na][1] + bi1 };
                *(float2*)(g_xw + ((size_t)b * T_ + t) * G4_ + n) = v;
            }
            {
                int t = m2 >> 5, b = m2 & 31;
                float2 v = { acc[ma][na][2] + bi0, acc[ma][na][3] + bi1 };
                *(float2*)(g_xw + ((size_t)b * T_ + t) * G4_ + n) = v;
            }
        }
    }
#undef LOADG
#undef STORES
}

// ---------------- stage 2: segment-parallel recurrence (f32x2 packed) ------
__device__ __forceinline__ float sigf(float x) {
    return 1.f / (1.f + __expf(-x));
}

// pack scalar into both halves of a 64-bit f32x2
__device__ __forceinline__ unsigned long long pk2(float x) {
    unsigned long long r;
    asm("mov.b64 %0, {%1, %1};" : "=l"(r) : "f"(x));
    return r;
}
// d = a * b + d  (packed fp32 pair, exact rn per lane)
__device__ __forceinline__ void fma2(unsigned long long& d,
                                     unsigned long long a,
                                     unsigned long long b) {
    asm("fma.rn.f32x2 %0, %1, %2, %0;" : "+l"(d) : "l"(a), "l"(b));
}
__device__ __forceinline__ float2 up2(unsigned long long v) {
    float2 f;
    asm("mov.b64 {%0, %1}, %2;" : "=f"(f.x), "=f"(f.y) : "l"(v));
    return f;
}

__global__ __launch_bounds__(512, 1) void k_recur(const int* __restrict__ reset,
                                                  const float* __restrict__ Wp,
                                                  const float* __restrict__ bp,
                                                  float* __restrict__ out) {
    // h interleaved by stream pair: hp[buf][pair][2*k + e], e = stream&1
    __shared__ float hp[2][NPAIR_][2 * H_];
    __shared__ float red[2][GS_][8];       // per-warp projection partials
    __shared__ int s_start[GS_], s_end[GS_], s_b[GS_];

    const int tid   = threadIdx.x;
    const int grp   = tid >> 8;            // 0/1: which 8 streams (4 pairs)
    const int j     = tid & 255;           // hidden unit 0..255
    const int lane  = tid & 31;
    const int warp8 = (tid >> 5) & 7;      // warp index within group
    const int sbase = grp * SPG_;
    const int pbase = grp * 4;             // first pair of this group

    if (tid < GS_) {
        int sid = blockIdx.x * GS_ + tid;
        int b = sid / P_;
        int k = sid % P_;
        s_start[tid] = g_bound[b][k];
        s_end[tid]   = g_bound[b][k + 1];
        s_b[tid]     = b;
    }
    // zero initial h
    for (int q = tid; q < NPAIR_ * 2 * H_; q += 512)
        ((float*)hp[0])[q] = 0.f;

    float c[SPG_];
#pragma unroll
    for (int s = 0; s < SPG_; s++) c[s] = 0.f;
    __syncthreads();

    int maxlen = 0;
#pragma unroll
    for (int s = 0; s < GS_; s++) {
        int len = s_end[s] - s_start[s];
        maxlen = max(maxlen, len);
    }

    const float wp  = Wp[j];
    const float bpv = bp[0];
    const float* __restrict__ wt = g_WT;

    for (int r = 0; r < maxlen; r++) {
        const int rb = r & 1;

        // acc2[gate][pair]: packed (stream_even, stream_odd) gate sums
        unsigned long long acc2[4][4];
#pragma unroll
        for (int g = 0; g < 4; g++)
#pragma unroll
            for (int p = 0; p < 4; p++) acc2[g][p] = 0ull;

        // gates += h @ W_hh^T ; weights broadcast into f32x2, h pre-paired
        for (int kk = 0; kk < H_; kk += 2) {
            const float* wr0 = wt + (size_t)kk * G4_ + j;
            const float* wr1 = wr0 + G4_;
            unsigned long long w2[4][2];
            w2[0][0] = pk2(wr0[0]);   w2[0][1] = pk2(wr1[0]);
            w2[1][0] = pk2(wr0[256]); w2[1][1] = pk2(wr1[256]);
            w2[2][0] = pk2(wr0[512]); w2[2][1] = pk2(wr1[512]);
            w2[3][0] = pk2(wr0[768]); w2[3][1] = pk2(wr1[768]);
#pragma unroll
            for (int p = 0; p < 4; p++) {
                ulonglong2 hv = *(const ulonglong2*)&hp[rb][pbase + p][2 * kk];
#pragma unroll
                for (int g = 0; g < 4; g++) {
                    fma2(acc2[g][p], w2[g][0], hv.x);
                    fma2(acc2[g][p], w2[g][1], hv.y);
                }
            }
        }

#pragma unroll
        for (int p = 0; p < 4; p++) {
            float2 ai = up2(acc2[0][p]);
            float2 af = up2(acc2[1][p]);
            float2 ag = up2(acc2[2][p]);
            float2 ao = up2(acc2[3][p]);
#pragma unroll
            for (int e = 0; e < 2; e++) {
                const int s  = 2 * p + e;          // stream within group
                const int ss = sbase + s;          // global stream in block
                int t = s_start[ss] + r;
                if (t < s_end[ss]) {               // uniform across block per ss
                    int b = s_b[ss];
                    const float* xr = g_xw + ((size_t)b * T_ + t) * G4_ + j;
                    float keep = (reset[t * B_ + b] != 0) ? 0.f : 1.f;
                    float vi = e ? ai.y : ai.x;
                    float vf = e ? af.y : af.x;
                    float vg = e ? ag.y : ag.x;
                    float vo = e ? ao.y : ao.x;
                    float gi = xr[0]   + keep * vi;
                    float gf = xr[256] + keep * vf;
                    float gg = xr[512] + keep * vg;
                    float go = xr[768] + keep * vo;
                    float cc = sigf(gf) * (c[s] * keep) + sigf(gi) * tanhf(gg);
                    float hh = sigf(go) * tanhf(cc);
                    c[s] = cc;
                    hp[rb ^ 1][pbase + p][2 * j + e] = hh;
                    float pr = hh * wp;
#pragma unroll
                    for (int off = 16; off; off >>= 1)
                        pr += __shfl_down_sync(0xffffffffu, pr, off);
                    if (lane == 0) red[rb][ss][warp8] = pr;
                } else {
                    hp[rb ^ 1][pbase + p][2 * j + e] = 0.f;
                }
            }
        }
        __syncthreads();

        if (tid < GS_) {
            int s = tid;
            int t = s_start[s] + r;
            if (t < s_end[s]) {
                float sum = bpv;
#pragma unroll
                for (int w2i = 0; w2i < 8; w2i++) sum += red[rb][s][w2i];
                out[t * B_ + s_b[s]] = sum;
            }
        }
    }
}

// ---------------- launch ----------------------------------------------------
extern "C" void kernel_launch(void* const* d_in, const int* in_sizes, int n_in,
                              void* d_out, int out_size) {
    const float* x     = (const float*)d_in[0];
    const int*   reset = (const int*)  d_in[1];
    const float* Wih   = (const float*)d_in[2];
    const float* Whh   = (const float*)d_in[3];
    const float* bih   = (const float*)d_in[4];
    const float* bhh   = (const float*)d_in[5];
    const float* Wp    = (const float*)d_in[6];
    const float* bp    = (const float*)d_in[7];
    float* out = (float*)d_out;

    k_bounds<<<B_, 128>>>(reset);
    k_prep<<<(H_ * G4_ + 255) / 256, 256>>>(Whh, bih, bhh);

    static int smem_set = 0;
    if (!smem_set) {
        cudaFuncSetAttribute(k_gemm_tf32,
                             cudaFuncAttributeMaxDynamicSharedMemorySize, 65536);
        smem_set = 1;
    }
    dim3 grid(G4_ / GBN, (T_ * B_) / GBM);
    k_gemm_tf32<<<grid, 256, 65536>>>(x, Wih);

    k_recur<<<NBLK_, 512>>>(reset, Wp, bp, out);
}

// round 6
// speedup vs baseline: 2.7012x; 1.3886x over previous
#include <cuda_runtime.h>
#include <cstdint>
#include <cstdio>

#define T_  4096
#define B_  32
#define D_  512
#define H_  256
#define G4_ 1024            // 4*H
#define P_  148             // time-chunks per batch row
#define SPB_ 32             // streams per block
#define NBLK_ ((B_ * P_) / SPB_)   // 148 blocks

// ---------------- scratch (static device globals; no allocations) ----------
__device__ float g_xw[(size_t)B_ * T_ * G4_];   // [b][t][col'] permuted: col'=4*j+q
__device__ float g_Wf[128 * 16 * 32 * 4];       // fragment-packed tf32 W_hh (1 MB)
__device__ float g_bb[G4_];                     // b_ih + b_hh (original order)
__device__ int   g_bound[B_][P_ + 1];           // chunk boundaries per batch row

__device__ __forceinline__ float tf32r(float x) {
    float r;
    asm("cvt.rna.tf32.f32 %0, %1;" : "=f"(r) : "f"(x));
    return r;
}

// ---------------- stage 0: chunk boundaries at reset points ----------------
__global__ void k_bounds(const int* __restrict__ reset) {
    int b = blockIdx.x;
    int k = threadIdx.x;
    if (k == 0) {
        g_bound[b][0] = 0;
    } else if (k < P_) {
        int t = (k * T_) / P_;
        while (t < T_ && reset[t * B_ + b] == 0) t++;
        g_bound[b][k] = t;          // either a reset point (state=0) or T
    } else if (k == P_) {
        g_bound[b][P_] = T_;
    }
}

// ---------------- stage 0b: pack W_hh into mma B-fragment order ------------
// g_Wf float4 at (ntile, kt2, lane): {b0(kt=2*kt2), b1(2*kt2), b0(2*kt2+1), b1(2*kt2+1)}
// b0 = WT'[kt*8+qid][col'], b1 = WT'[kt*8+qid+4][col'], col' = ntile*8+gid,
// WT'[k][4*j+q] = W_hh[q*256 + j][k]   (tf32-rounded)
__global__ void k_prep(const float* __restrict__ Whh,
                       const float* __restrict__ bih,
                       const float* __restrict__ bhh) {
    int idx = blockIdx.x * blockDim.x + threadIdx.x;   // over 262144
    if (idx < 128 * 16 * 32 * 4) {
        int e     = idx & 3;
        int lane  = (idx >> 2) & 31;
        int kt2   = (idx >> 7) & 15;
        int ntile = idx >> 11;
        int gid = lane >> 2, qid = lane & 3;
        int colp = ntile * 8 + gid;
        int j = colp >> 2, q = colp & 3;
        int kt = kt2 * 2 + (e >> 1);
        int kk = kt * 8 + qid + (e & 1) * 4;
        g_Wf[idx] = tf32r(Whh[(q * 256 + j) * H_ + kk]);
    }
    if (idx < G4_) g_bb[idx] = bih[idx] + bhh[idx];
}

// ---------------- stage 1: xW GEMM via tf32 mma.sync -----------------------
#define GBM 128
#define GBN 128
#define GBK 32
#define BOFF (2 * GBM * GBK)   // Bs offset in dynamic smem (floats)

__device__ __forceinline__ void mma_tf32(float* c, const uint32_t* a, const uint32_t* b) {
    asm volatile(
        "mma.sync.aligned.m16n8k8.row.col.f32.tf32.tf32.f32 "
        "{%0,%1,%2,%3},{%4,%5,%6,%7},{%8,%9},{%0,%1,%2,%3};"
        : "+f"(c[0]), "+f"(c[1]), "+f"(c[2]), "+f"(c[3])
        : "r"(a[0]), "r"(a[1]), "r"(a[2]), "r"(a[3]), "r"(b[0]), "r"(b[1]));
}

__global__ __launch_bounds__(256) void k_gemm_tf32(const float* __restrict__ A,
                                                   const float* __restrict__ Bw) {
    extern __shared__ float sm[];   // As: [2][128][32] swizzled, Bs: same, 64 KB

    const int tid  = threadIdx.x;
    const int warp = tid >> 5;
    const int lane = tid & 31;
    const int wm   = warp >> 1;          // 0..3
    const int wn   = warp & 1;           // 0..1
    const int gid  = lane >> 2;          // groupID 0..7
    const int qid  = lane & 3;           // thread-in-group 0..3
    const int m0   = blockIdx.y * GBM;
    const int n0   = blockIdx.x * GBN;

    const int crow = tid >> 1;
    const int cc4  = (tid & 1) * 4;
    const float* gA = A  + (size_t)(m0 + crow) * D_ + cc4 * 4;
    const float* gB = Bw + (size_t)(n0 + crow) * D_ + cc4 * 4;

    float acc[2][8][4];
#pragma unroll
    for (int i = 0; i < 2; i++)
#pragma unroll
        for (int j = 0; j < 8; j++)
#pragma unroll
            for (int q = 0; q < 4; q++) acc[i][j][q] = 0.f;

    float4 ra[4], rb[4];

#define LOADG(k0)                                                   \
    {                                                               \
        _Pragma("unroll")                                           \
        for (int i = 0; i < 4; i++) {                               \
            ra[i] = *(const float4*)(gA + (k0) + i * 4);            \
            rb[i] = *(const float4*)(gB + (k0) + i * 4);            \
        }                                                           \
    }

#define STORES(buf)                                                             \
    {                                                                           \
        _Pragma("unroll")                                                       \
        for (int i = 0; i < 4; i++) {                                           \
            int sw = ((cc4 + i) ^ (crow & 7)) * 4;                              \
            float4 va;                                                          \
            va.x = tf32r(ra[i].x); va.y = tf32r(ra[i].y);                       \
            va.z = tf32r(ra[i].z); va.w = tf32r(ra[i].w);                       \
            *(float4*)&sm[((buf) * GBM + crow) * GBK + sw] = va;                \
            float4 vb;                                                          \
            vb.x = tf32r(rb[i].x); vb.y = tf32r(rb[i].y);                       \
            vb.z = tf32r(rb[i].z); vb.w = tf32r(rb[i].w);                       \
            *(float4*)&sm[BOFF + ((buf) * GBN + crow) * GBK + sw] = vb;         \
        }                                                                       \
    }

    LOADG(0)
    STORES(0)
    __syncthreads();

    const int NKT = D_ / GBK;   // 16
    for (int kt = 0; kt < NKT; kt++) {
        const int cur = kt & 1;
        if (kt + 1 < NKT) LOADG((kt + 1) * GBK)

#pragma unroll
        for (int kc = 0; kc < 4; kc++) {
            const int k4a = kc * 2;
            uint32_t af[2][4], bf[8][2];
#pragma unroll
            for (int ma = 0; ma < 2; ma++) {
                int rw = wm * 32 + ma * 16 + gid;
                int b0 = (cur * GBM + rw) * GBK;
                int b8 = b0 + 8 * GBK;
                int x  = rw & 7;
                af[ma][0] = __float_as_uint(sm[b0 + ((k4a)     ^ x) * 4 + qid]);
                af[ma][1] = __float_as_uint(sm[b8 + ((k4a)     ^ x) * 4 + qid]);
                af[ma][2] = __float_as_uint(sm[b0 + ((k4a + 1) ^ x) * 4 + qid]);
                af[ma][3] = __float_as_uint(sm[b8 + ((k4a + 1) ^ x) * 4 + qid]);
            }
#pragma unroll
            for (int na = 0; na < 8; na++) {
                int rn = wn * 64 + na * 8 + gid;
                int bb = BOFF + (cur * GBN + rn) * GBK;
                int x  = rn & 7;
                bf[na][0] = __float_as_uint(sm[bb + ((k4a)     ^ x) * 4 + qid]);
                bf[na][1] = __float_as_uint(sm[bb + ((k4a + 1) ^ x) * 4 + qid]);
            }
#pragma unroll
            for (int na = 0; na < 8; na++)
#pragma unroll
                for (int ma = 0; ma < 2; ma++)
                    mma_tf32(acc[ma][na], af[ma], bf[na]);
        }

        if (kt + 1 < NKT) STORES(cur ^ 1)
        __syncthreads();
    }

    // epilogue: +bias, scatter to PERMUTED cols: n -> 4*(n&255) + (n>>8)
#pragma unroll
    for (int na = 0; na < 8; na++) {
        const int n = n0 + wn * 64 + na * 8 + qid * 2;
        const float bi0 = g_bb[n];
        const float bi1 = g_bb[n + 1];
        const int cp0 = 4 * (n & 255) + (n >> 8);
        const int cp1 = cp0 + 4;
#pragma unroll
        for (int ma = 0; ma < 2; ma++) {
            int m1 = m0 + wm * 32 + ma * 16 + gid;
            int m2 = m1 + 8;
            {
                int t = m1 >> 5, b = m1 & 31;
                float* dst = g_xw + ((size_t)b * T_ + t) * G4_;
                dst[cp0] = acc[ma][na][0] + bi0;
                dst[cp1] = acc[ma][na][1] + bi1;
            }
            {
                int t = m2 >> 5, b = m2 & 31;
                float* dst = g_xw + ((size_t)b * T_ + t) * G4_;
                dst[cp0] = acc[ma][na][2] + bi0;
                dst[cp1] = acc[ma][na][3] + bi1;
            }
        }
    }
#undef LOADG
#undef STORES
}

// ---------------- stage 2: tensor-core segment-parallel recurrence ---------
__device__ __forceinline__ float sigf(float x) {
    return 1.f / (1.f + __expf(-x));
}

#define HSTR 260               // h row stride (floats): 256 + pad 4 (conflict-free frags)
#define HSBUF (SPB_ * HSTR)    // one h buffer

__global__ __launch_bounds__(512, 1) void k_recur(const int* __restrict__ reset,
                                                  const float* __restrict__ Wp,
                                                  const float* __restrict__ bp,
                                                  float* __restrict__ out) {
    extern __shared__ float smr[];
    float* hs  = smr;                       // [2][32][260]
    float* red = smr + 2 * HSBUF;           // [32][16]
    int*   meta = (int*)(red + 32 * 16);
    int* s_start = meta;
    int* s_end   = meta + 32;
    int* s_b     = meta + 64;

    const int tid  = threadIdx.x;
    const int w    = tid >> 5;              // warp 0..15 -> ntiles w*8..w*8+7
    const int lane = tid & 31;
    const int gid  = lane >> 2;
    const int qid  = lane & 3;

    if (tid < 32) {
        int sid = blockIdx.x * SPB_ + tid;
        int b = sid / P_;
        int k = sid % P_;
        s_start[tid] = g_bound[b][k];
        s_end[tid]   = g_bound[b][k + 1];
        s_b[tid]     = b;
    }
    for (int q = tid; q < HSBUF; q += 512) hs[q] = 0.f;   // zero h buffer 0
    __syncthreads();

    // fixed per-thread stream identities: s = mt*16 + gid + 8*(qid&1)
    const int sA = gid + 8 * (qid & 1);
    const int sB = sA + 16;
    const int stA = s_start[sA], enA = s_end[sA], bA = s_b[sA];
    const int stB = s_start[sB], enB = s_end[sB], bB = s_b[sB];

    int maxlen = 0;
    for (int s = 0; s < 32; s++) maxlen = max(maxlen, s_end[s] - s_start[s]);

    // per-thread j per ntile index: j = (w*8+ni)*2 + (qid>>1)
    float wp8[8];
#pragma unroll
    for (int i = 0; i < 8; i++) wp8[i] = Wp[(w * 8 + i) * 2 + (qid >> 1)];
    const float bpv = bp[0];

    float cell[8][2];
#pragma unroll
    for (int i = 0; i < 8; i++) { cell[i][0] = 0.f; cell[i][1] = 0.f; }

    const float4* wf = (const float4*)g_Wf;

    for (int r = 0; r < maxlen; r++) {
        const int rb = r & 1;
        const float* hcur = hs + rb * HSBUF;
        float*       hnxt = hs + (rb ^ 1) * HSBUF;

        const int tA = stA + r;
        const int tB = stB + r;
        const bool actA = tA < enA;
        const bool actB = tB < enB;
        float keepA = 0.f, keepB = 0.f;
        const float* xrA = g_xw;
        const float* xrB = g_xw;
        if (actA) {
            keepA = (reset[tA * B_ + bA] != 0) ? 0.f : 1.f;
            xrA = g_xw + ((size_t)bA * T_ + tA) * G4_;
        }
        if (actB) {
            keepB = (reset[tB * B_ + bB] != 0) ? 0.f : 1.f;
            xrB = g_xw + ((size_t)bB * T_ + tB) * G4_;
        }

        float prjA = 0.f, prjB = 0.f;

#pragma unroll
        for (int half = 0; half < 2; half++) {
            float cacc[4][2][4];
#pragma unroll
            for (int nt = 0; nt < 4; nt++)
#pragma unroll
                for (int mt = 0; mt < 2; mt++)
#pragma unroll
                    for (int q = 0; q < 4; q++) cacc[nt][mt][q] = 0.f;

            // gate GEMM: gates[32 x (this warp's 32 cols)] += h @ WT'
            for (int kt2 = 0; kt2 < 16; kt2++) {
                float4 bv[4];
#pragma unroll
                for (int nt = 0; nt < 4; nt++)
                    bv[nt] = wf[((w * 8 + half * 4 + nt) * 16 + kt2) * 32 + lane];

                uint32_t a[2][2][4];
#pragma unroll
                for (int sub = 0; sub < 2; sub++) {
                    const int kc = (kt2 * 2 + sub) * 8 + qid;
#pragma unroll
                    for (int mt = 0; mt < 2; mt++) {
                        const float* hb = hcur + (mt * 16 + gid) * HSTR;
                        a[sub][mt][0] = __float_as_uint(hb[kc]);
                        a[sub][mt][1] = __float_as_uint(hb[8 * HSTR + kc]);
                        a[sub][mt][2] = __float_as_uint(hb[kc + 4]);
                        a[sub][mt][3] = __float_as_uint(hb[8 * HSTR + kc + 4]);
                    }
                }
#pragma unroll
                for (int nt = 0; nt < 4; nt++) {
                    uint32_t be[2] = { __float_as_uint(bv[nt].x), __float_as_uint(bv[nt].y) };
                    uint32_t bo[2] = { __float_as_uint(bv[nt].z), __float_as_uint(bv[nt].w) };
#pragma unroll
                    for (int mt = 0; mt < 2; mt++) {
                        mma_tf32(cacc[nt][mt], a[0][mt], be);
                        mma_tf32(cacc[nt][mt], a[1][mt], bo);
                    }
                }
            }

            // pointwise LSTM for this half's 4 ntiles
#pragma unroll
            for (int nt = 0; nt < 4; nt++) {
                const int ni = half * 4 + nt;
                const int j  = (w * 8 + ni) * 2 + (qid >> 1);
#pragma unroll
                for (int mt = 0; mt < 2; mt++) {
                    float* C = cacc[nt][mt];
                    // gate exchange between qid-pairs: even owns (i,f), odd (g,o)
                    float sx = (qid & 1) ? C[0] : C[2];
                    float sy = (qid & 1) ? C[1] : C[3];
                    float rx = __shfl_xor_sync(0xffffffffu, sx, 1);
                    float ry = __shfl_xor_sync(0xffffffffu, sy, 1);
                    float gi, gf, gg, go;
                    if (qid & 1) { gi = rx;   gf = ry;   gg = C[2]; go = C[3]; }
                    else         { gi = C[0]; gf = C[1]; gg = rx;   go = ry;  }

                    const bool  act  = mt ? actB : actA;
                    const float keep = mt ? keepB : keepA;
                    const float* xr  = mt ? xrB : xrA;
                    float hh = 0.f;
                    if (act) {
                        float4 xv = *(const float4*)(xr + 4 * j);
                        float vi = xv.x + keep * gi;
                        float vf = xv.y + keep * gf;
                        float vg = xv.z + keep * gg;
                        float vo = xv.w + keep * go;
                        float cc = sigf(vf) * (cell[ni][mt] * keep) + sigf(vi) * tanhf(vg);
                        hh = sigf(vo) * tanhf(cc);
                        cell[ni][mt] = cc;
                        if (mt) prjB += wp8[ni] * hh;
                        else    prjA += wp8[ni] * hh;
                    }
                    const int s = mt ? sB : sA;
                    hnxt[s * HSTR + j] = tf32r(hh);
                }
            }
        }

        // projection: combine the two j-halves (qid ^ 2 shares the same stream)
        prjA += __shfl_xor_sync(0xffffffffu, prjA, 2);
        prjB += __shfl_xor_sync(0xffffffffu, prjB, 2);
        if (qid < 2) {
            red[sA * 16 + w] = prjA;
            red[sB * 16 + w] = prjB;
        }
        __syncthreads();

        if (tid < 32) {
            int t = s_start[tid] + r;
            if (t < s_end[tid]) {
                float sum = bpv;
#pragma unroll
                for (int i = 0; i < 16; i++) sum += red[tid * 16 + i];
                out[t * B_ + s_b[tid]] = sum;
            }
        }
        __syncthreads();
    }
}

// ---------------- launch ----------------------------------------------------
extern "C" void kernel_launch(void* const* d_in, const int* in_sizes, int n_in,
                              void* d_out, int out_size) {
    const float* x     = (const float*)d_in[0];
    const int*   reset = (const int*)  d_in[1];
    const float* Wih   = (const float*)d_in[2];
    const float* Whh   = (const float*)d_in[3];
    const float* bih   = (const float*)d_in[4];
    const float* bhh   = (const float*)d_in[5];
    const float* Wp    = (const float*)d_in[6];
    const float* bp    = (const float*)d_in[7];
    float* out = (float*)d_out;

    static int attr_set = 0;
    if (!attr_set) {
        cudaFuncSetAttribute(k_gemm_tf32,
                             cudaFuncAttributeMaxDynamicSharedMemorySize, 65536);
        cudaFuncSetAttribute(k_recur,
                             cudaFuncAttributeMaxDynamicSharedMemorySize, 73728);
        attr_set = 1;
    }

    k_bounds<<<B_, 160>>>(reset);
    k_prep<<<1024, 256>>>(Whh, bih, bhh);

    dim3 grid(G4_ / GBN, (T_ * B_) / GBM);
    k_gemm_tf32<<<grid, 256, 65536>>>(x, Wih);

    const int rsm = (2 * HSBUF + 32 * 16) * 4 + 96 * 4;
    k_recur<<<NBLK_, 512, rsm>>>(reset, Wp, bp, out);
}